// round 2
// baseline (speedup 1.0000x reference)
#include <cuda_runtime.h>
#include <math.h>
#include <stdint.h>

#define BB 16
#define NN 1024
#define DD 64

#define LOGN 6.931471805599453f   /* ln(1024) */

// ---------------- scratch (static device globals; no allocations) ----------
__device__ float g_C[BB * NN * NN];        // 64 MB cost matrix (clamped C)
__device__ float g_x2[BB * NN];
__device__ float g_y2[BB * NN];
__device__ float g_logu[BB * NN];
__device__ float g_logv[BB * NN];
__device__ unsigned int g_cminbits[BB];
__device__ float g_inv_eps;

// ---------------- helpers ---------------------------------------------------
__device__ __forceinline__ float read_eps(const void* p) {
    // eps may arrive as float32 or int32 (python scalar). Int 1 reinterpreted
    // as float is a denormal ~1.4e-45, so use magnitude heuristic.
    float f = *(const float*)p;
    if (isfinite(f) && fabsf(f) > 1e-20f && fabsf(f) < 1e20f) return f;
    return (float)(*(const int*)p);
}

__device__ __forceinline__ void lse_update(float v, float& mx, float& s) {
    if (v <= mx) {
        s += __expf(v - mx);
    } else {
        s = s * __expf(mx - v) + 1.0f;
        mx = v;
    }
}

__device__ __forceinline__ void lse_combine(float m2, float s2, float& mx, float& s) {
    float M = fmaxf(mx, m2);
    s = s * __expf(mx - M) + s2 * __expf(m2 - M);
    mx = M;
}

// ---------------- prep: x2, y2, init state ----------------------------------
__global__ void k_prep(const float* __restrict__ x, const float* __restrict__ y,
                       const void* __restrict__ epsp) {
    int idx = blockIdx.x * blockDim.x + threadIdx.x;
    if (idx == 0) {
        float e = read_eps(epsp);
        g_inv_eps = 1.0f / e;
    }
    if (idx < BB) g_cminbits[idx] = 0x7F800000u;  // +inf bits
    if (idx < BB * NN) {
        const float4* xr = (const float4*)(x + (size_t)idx * DD);
        float s = 0.0f;
#pragma unroll
        for (int j = 0; j < DD / 4; j++) {
            float4 v = xr[j];
            s += v.x * v.x + v.y * v.y + v.z * v.z + v.w * v.w;
        }
        g_x2[idx] = s;
        g_logu[idx] = 0.0f;
    } else if (idx < 2 * BB * NN) {
        int j2 = idx - BB * NN;
        const float4* yr = (const float4*)(y + (size_t)j2 * DD);
        float s = 0.0f;
#pragma unroll
        for (int j = 0; j < DD / 4; j++) {
            float4 v = yr[j];
            s += v.x * v.x + v.y * v.y + v.z * v.z + v.w * v.w;
        }
        g_y2[j2] = s;
        g_logv[j2] = 0.0f;
    }
}

// ---------------- C = max(x2 + y2 - 2 x.y, 0); track per-batch min ----------
// Tile 64(n) x 64(m), k=64 full. 256 threads, each computes 4x4.
__global__ void k_gemm(const float* __restrict__ x, const float* __restrict__ y) {
    __shared__ float xs[64][65];
    __shared__ float ys[64][65];
    __shared__ float wmin[8];

    const int b  = blockIdx.z;
    const int n0 = blockIdx.y * 64;
    const int m0 = blockIdx.x * 64;
    const int t  = threadIdx.x;

    // load tiles (each thread: 4 float4 from x, 4 from y)
    {
        int row = t >> 4;
        int col = (t & 15) * 4;
#pragma unroll
        for (int rr = 0; rr < 4; rr++) {
            int r = row + 16 * rr;
            float4 vx = *(const float4*)(x + ((size_t)(b * NN + n0 + r)) * DD + col);
            xs[r][col + 0] = vx.x; xs[r][col + 1] = vx.y;
            xs[r][col + 2] = vx.z; xs[r][col + 3] = vx.w;
            float4 vy = *(const float4*)(y + ((size_t)(b * NN + m0 + r)) * DD + col);
            ys[r][col + 0] = vy.x; ys[r][col + 1] = vy.y;
            ys[r][col + 2] = vy.z; ys[r][col + 3] = vy.w;
        }
    }
    __syncthreads();

    const int tn = t >> 4;   // 0..15
    const int tm = t & 15;   // 0..15
    float acc[4][4];
#pragma unroll
    for (int i = 0; i < 4; i++)
#pragma unroll
        for (int j = 0; j < 4; j++) acc[i][j] = 0.0f;

#pragma unroll 8
    for (int k = 0; k < 64; k++) {
        float a[4], bb_[4];
#pragma unroll
        for (int i = 0; i < 4; i++) a[i] = xs[tn * 4 + i][k];
#pragma unroll
        for (int j = 0; j < 4; j++) bb_[j] = ys[tm * 4 + j][k];
#pragma unroll
        for (int i = 0; i < 4; i++)
#pragma unroll
            for (int j = 0; j < 4; j++) acc[i][j] += a[i] * bb_[j];
    }

    float tmin = INFINITY;
#pragma unroll
    for (int i = 0; i < 4; i++) {
        int n = n0 + tn * 4 + i;
        float xx = g_x2[b * NN + n];
        float4 cv;
        float c[4];
#pragma unroll
        for (int j = 0; j < 4; j++) {
            int m = m0 + tm * 4 + j;
            float v = xx + g_y2[b * NN + m] - 2.0f * acc[i][j];
            v = fmaxf(v, 0.0f);
            c[j] = v;
            tmin = fminf(tmin, v);
        }
        cv.x = c[0]; cv.y = c[1]; cv.z = c[2]; cv.w = c[3];
        *(float4*)(g_C + ((size_t)(b * NN + n)) * NN + m0 + tm * 4) = cv;
    }

    // block-level min -> atomicMin (float bits; all values >= 0 so unsigned
    // bit ordering == float ordering)
#pragma unroll
    for (int off = 16; off > 0; off >>= 1)
        tmin = fminf(tmin, __shfl_xor_sync(0xFFFFFFFFu, tmin, off));
    if ((t & 31) == 0) wmin[t >> 5] = tmin;
    __syncthreads();
    if (t == 0) {
        float bm = wmin[0];
#pragma unroll
        for (int w = 1; w < 8; w++) bm = fminf(bm, wmin[w]);
        atomicMin(&g_cminbits[b], __float_as_uint(bm));
    }
}

// ---------------- column pass: log_v[m] = logb - LSE_n(k[n,m] + log_u[n]) ---
// 512 threads: 64 columns x 8 row-partitions of 128 rows each.
__global__ void k_col() {
    __shared__ float smx[8][64];
    __shared__ float ssum[8][64];

    const int b  = blockIdx.y;
    const int m0 = blockIdx.x * 64;
    const int t  = threadIdx.x;
    const int c  = t & 63;
    const int p  = t >> 6;
    const int m  = m0 + c;

    const float cmin = __uint_as_float(g_cminbits[b]);
    const float inv  = g_inv_eps;

    const float* Cb = g_C + (size_t)b * NN * NN;
    const float* LU = g_logu + b * NN;

    float mx = -INFINITY, s = 0.0f;
    const int nbeg = p * 128;
#pragma unroll 2
    for (int n = nbeg; n < nbeg + 128; n += 4) {
        float c0 = Cb[(size_t)(n + 0) * NN + m];
        float c1 = Cb[(size_t)(n + 1) * NN + m];
        float c2 = Cb[(size_t)(n + 2) * NN + m];
        float c3 = Cb[(size_t)(n + 3) * NN + m];
        float u0 = LU[n + 0], u1 = LU[n + 1], u2 = LU[n + 2], u3 = LU[n + 3];
        lse_update((cmin - c0) * inv + u0, mx, s);
        lse_update((cmin - c1) * inv + u1, mx, s);
        lse_update((cmin - c2) * inv + u2, mx, s);
        lse_update((cmin - c3) * inv + u3, mx, s);
    }
    smx[p][c] = mx;
    ssum[p][c] = s;
    __syncthreads();

    if (t < 64) {
        float M = smx[0][t], S = ssum[0][t];
#pragma unroll
        for (int q = 1; q < 8; q++) lse_combine(smx[q][t], ssum[q][t], M, S);
        g_logv[b * NN + m0 + t] = -LOGN - (M + __logf(S));
    }
}

// ---------------- row pass: log_u[n] = loga - LSE_m(k[n,m] + log_v[m]) -----
// 256 threads = 8 warps, one warp per row.
__global__ void k_row() {
    const int b = blockIdx.y;
    const int t = threadIdx.x;
    const int lane = t & 31;
    const int row  = blockIdx.x * 8 + (t >> 5);

    const float cmin = __uint_as_float(g_cminbits[b]);
    const float inv  = g_inv_eps;

    const float4* Crow = (const float4*)(g_C + ((size_t)(b * NN + row)) * NN);
    const float4* LV   = (const float4*)(g_logv + b * NN);

    float mx = -INFINITY, s = 0.0f;
#pragma unroll
    for (int j = 0; j < 8; j++) {
        int i4 = lane + 32 * j;
        float4 cv = Crow[i4];
        float4 lv = LV[i4];
        lse_update((cmin - cv.x) * inv + lv.x, mx, s);
        lse_update((cmin - cv.y) * inv + lv.y, mx, s);
        lse_update((cmin - cv.z) * inv + lv.z, mx, s);
        lse_update((cmin - cv.w) * inv + lv.w, mx, s);
    }
#pragma unroll
    for (int off = 16; off > 0; off >>= 1) {
        float om = __shfl_down_sync(0xFFFFFFFFu, mx, off);
        float os = __shfl_down_sync(0xFFFFFFFFu, s, off);
        lse_combine(om, os, mx, s);
    }
    if (lane == 0) g_logu[b * NN + row] = -LOGN - (mx + __logf(s));
}

// ---------------- output: out[n,:] = (sum_m P[n,m] y[m,:]) / sum_m P[n,m] ---
// Block: 16 rows x 64-wide m-tiles; 256 threads.
__global__ void k_out(const float* __restrict__ y, float* __restrict__ out) {
    __shared__ __align__(16) float ysm[64 * 64];   // y tile [mm][d]
    __shared__ __align__(16) float wt[16 * 64];    // w tile [r][mm]

    const int b  = blockIdx.y;
    const int n0 = blockIdx.x * 16;
    const int t  = threadIdx.x;
    const int r  = t >> 4;    // 0..15 output row
    const int dg = t & 15;    // 0..15 -> d = dg*4..dg*4+3

    const float cmin = __uint_as_float(g_cminbits[b]);
    const float inv  = g_inv_eps;

    float4 acc = make_float4(0.f, 0.f, 0.f, 0.f);
    float wsum = 0.0f;

    for (int mt = 0; mt < NN; mt += 64) {
        // load y tile: 64 rows x 64 cols = 1024 float4, 4 per thread
#pragma unroll
        for (int r2 = 0; r2 < 4; r2++) {
            int fid = t + 256 * r2;
            int row = fid >> 4;
            int col4 = fid & 15;
            ((float4*)ysm)[fid] =
                *(const float4*)(y + ((size_t)(b * NN + mt + row)) * DD + col4 * 4);
        }
        // compute w tile: 1024 values, 4 per thread (one float4 of C)
        {
            int wid = t * 4;
            int rw = wid >> 6;
            int mmw = wid & 63;
            float4 cv = *(const float4*)(g_C + ((size_t)(b * NN + n0 + rw)) * NN + mt + mmw);
            float4 lv = *(const float4*)(g_logv + b * NN + mt + mmw);
            float lu = g_logu[b * NN + n0 + rw];
            float4 wv;
            wv.x = __expf(lu + (cmin - cv.x) * inv + lv.x);
            wv.y = __expf(lu + (cmin - cv.y) * inv + lv.y);
            wv.z = __expf(lu + (cmin - cv.z) * inv + lv.z);
            wv.w = __expf(lu + (cmin - cv.w) * inv + lv.w);
            *(float4*)(wt + wid) = wv;
        }
        __syncthreads();

#pragma unroll 16
        for (int mm = 0; mm < 64; mm++) {
            float w = wt[r * 64 + mm];
            float4 yv = *(const float4*)(ysm + mm * 64 + dg * 4);
            acc.x += w * yv.x;
            acc.y += w * yv.y;
            acc.z += w * yv.z;
            acc.w += w * yv.w;
            wsum += w;
        }
        __syncthreads();
    }

    float rinv = 1.0f / fmaxf(wsum, 1e-12f);
    float4 o;
    o.x = acc.x * rinv; o.y = acc.y * rinv;
    o.z = acc.z * rinv; o.w = acc.w * rinv;
    *(float4*)(out + ((size_t)(b * NN + n0 + r)) * DD + dg * 4) = o;
}

// ---------------- launcher ---------------------------------------------------
extern "C" void kernel_launch(void* const* d_in, const int* in_sizes, int n_in,
                              void* d_out, int out_size) {
    const float* x = (const float*)d_in[0];
    const float* y = (const float*)d_in[1];
    const void* eps = d_in[2];
    float* out = (float*)d_out;

    k_prep<<<(2 * BB * NN + 255) / 256, 256>>>(x, y, eps);
    k_gemm<<<dim3(NN / 64, NN / 64, BB), 256>>>(x, y);

    for (int it = 0; it < 50; it++) {
        k_col<<<dim3(NN / 64, BB), 512>>>();
        k_row<<<dim3(NN / 8, BB), 256>>>();
    }
    k_col<<<dim3(NN / 64, BB), 512>>>();  // final v-update

    k_out<<<dim3(NN / 16, BB), 256>>>(y, out);
}

// round 3
// speedup vs baseline: 1.8584x; 1.8584x over previous
#include <cuda_runtime.h>
#include <math.h>
#include <stdint.h>

#define BB 16
#define NN 1024
#define DD 64
#define LOG2E 1.4426950408889634f

// ---------------- scratch (static device globals; no allocations) ----------
__device__ float g_C[BB * NN * NN];   // C2 = -C * inv_eps * LOG2E  (<= 0)
__device__ float g_x2[BB * NN];
__device__ float g_y2[BB * NN];
__device__ float g_Lu2[BB * NN];      // (log_u + cmin/eps) * LOG2E
__device__ float g_Lv2[BB * NN];      // (log_v + cmin/eps) * LOG2E
__device__ unsigned int g_cminbits[BB];
__device__ float g_inv_eps;

// ---------------- helpers ---------------------------------------------------
__device__ __forceinline__ float read_eps(const void* p) {
    float f = *(const float*)p;
    if (isfinite(f) && fabsf(f) > 1e-20f && fabsf(f) < 1e20f) return f;
    return (float)(*(const int*)p);
}

// ---------------- prep: x2, y2, eps, cmin init ------------------------------
__global__ void k_prep(const float* __restrict__ x, const float* __restrict__ y,
                       const void* __restrict__ epsp) {
    int idx = blockIdx.x * blockDim.x + threadIdx.x;
    if (idx == 0) g_inv_eps = 1.0f / read_eps(epsp);
    if (idx < BB) g_cminbits[idx] = 0x7F800000u;  // +inf
    if (idx < BB * NN) {
        const float4* xr = (const float4*)(x + (size_t)idx * DD);
        float s = 0.0f;
#pragma unroll
        for (int j = 0; j < DD / 4; j++) {
            float4 v = xr[j];
            s += v.x * v.x + v.y * v.y + v.z * v.z + v.w * v.w;
        }
        g_x2[idx] = s;
    } else if (idx < 2 * BB * NN) {
        int j2 = idx - BB * NN;
        const float4* yr = (const float4*)(y + (size_t)j2 * DD);
        float s = 0.0f;
#pragma unroll
        for (int j = 0; j < DD / 4; j++) {
            float4 v = yr[j];
            s += v.x * v.x + v.y * v.y + v.z * v.z + v.w * v.w;
        }
        g_y2[j2] = s;
    }
}

// ---------------- C2 = -max(x2+y2-2x.y,0)*inv_eps*LOG2E; track raw min ------
__global__ void k_gemm(const float* __restrict__ x, const float* __restrict__ y) {
    __shared__ float xs[64][65];
    __shared__ float ys[64][65];
    __shared__ float wmin[8];

    const int b  = blockIdx.z;
    const int n0 = blockIdx.y * 64;
    const int m0 = blockIdx.x * 64;
    const int t  = threadIdx.x;

    {
        int row = t >> 4;
        int col = (t & 15) * 4;
#pragma unroll
        for (int rr = 0; rr < 4; rr++) {
            int r = row + 16 * rr;
            float4 vx = *(const float4*)(x + ((size_t)(b * NN + n0 + r)) * DD + col);
            xs[r][col + 0] = vx.x; xs[r][col + 1] = vx.y;
            xs[r][col + 2] = vx.z; xs[r][col + 3] = vx.w;
            float4 vy = *(const float4*)(y + ((size_t)(b * NN + m0 + r)) * DD + col);
            ys[r][col + 0] = vy.x; ys[r][col + 1] = vy.y;
            ys[r][col + 2] = vy.z; ys[r][col + 3] = vy.w;
        }
    }
    __syncthreads();

    const int tn = t >> 4;
    const int tm = t & 15;
    float acc[4][4];
#pragma unroll
    for (int i = 0; i < 4; i++)
#pragma unroll
        for (int j = 0; j < 4; j++) acc[i][j] = 0.0f;

#pragma unroll 8
    for (int k = 0; k < 64; k++) {
        float a[4], bb_[4];
#pragma unroll
        for (int i = 0; i < 4; i++) a[i] = xs[tn * 4 + i][k];
#pragma unroll
        for (int j = 0; j < 4; j++) bb_[j] = ys[tm * 4 + j][k];
#pragma unroll
        for (int i = 0; i < 4; i++)
#pragma unroll
            for (int j = 0; j < 4; j++) acc[i][j] += a[i] * bb_[j];
    }

    const float negScale = -g_inv_eps * LOG2E;
    float tmin = INFINITY;
#pragma unroll
    for (int i = 0; i < 4; i++) {
        int n = n0 + tn * 4 + i;
        float xx = g_x2[b * NN + n];
        float4 cv;
        float c[4];
#pragma unroll
        for (int j = 0; j < 4; j++) {
            int m = m0 + tm * 4 + j;
            float v = xx + g_y2[b * NN + m] - 2.0f * acc[i][j];
            v = fmaxf(v, 0.0f);
            tmin = fminf(tmin, v);
            c[j] = v * negScale;
        }
        cv.x = c[0]; cv.y = c[1]; cv.z = c[2]; cv.w = c[3];
        *(float4*)(g_C + ((size_t)(b * NN + n)) * NN + m0 + tm * 4) = cv;
    }

#pragma unroll
    for (int off = 16; off > 0; off >>= 1)
        tmin = fminf(tmin, __shfl_xor_sync(0xFFFFFFFFu, tmin, off));
    if ((t & 31) == 0) wmin[t >> 5] = tmin;
    __syncthreads();
    if (t == 0) {
        float bm = wmin[0];
#pragma unroll
        for (int w = 1; w < 8; w++) bm = fminf(bm, wmin[w]);
        atomicMin(&g_cminbits[b], __float_as_uint(bm));
    }
}

// ---------------- init Lu2/Lv2 = cmin*inv_eps*LOG2E (log_u = log_v = 0) -----
__global__ void k_init() {
    int idx = blockIdx.x * blockDim.x + threadIdx.x;
    if (idx < BB * NN) {
        int b = idx >> 10;
        float cminv2 = __uint_as_float(g_cminbits[b]) * g_inv_eps * LOG2E;
        g_Lu2[idx] = cminv2;
        g_Lv2[idx] = cminv2;
    }
}

// ---------------- column pass ------------------------------------------------
// Lv2_new[m] = Cv - (V0 + log2(sum_n exp2(C2[n,m] + Lu2[n] - V0)))
// Block: 64 columns x full 1024 rows. 512 threads = 16 col-groups(x4) x 32 row parts.
__global__ void k_col() {
    __shared__ float lu2s[NN];
    __shared__ float4 part[32][16];

    const int b  = blockIdx.y;
    const int m0 = blockIdx.x * 64;
    const int t  = threadIdx.x;
    const int g  = t & 15;   // column group (4 cols)
    const int p  = t >> 4;   // row partition (32 rows)

    lu2s[t]       = g_Lu2[b * NN + t];
    lu2s[t + 512] = g_Lu2[b * NN + t + 512];

    const float cminv2 = __uint_as_float(g_cminbits[b]) * g_inv_eps * LOG2E;
    const float Cv = cminv2 - 10.0f;   // - log2(1024)

    float4 pl = *(const float4*)(g_Lv2 + b * NN + m0 + 4 * g);
    float4 V0;
    V0.x = Cv - pl.x; V0.y = Cv - pl.y; V0.z = Cv - pl.z; V0.w = Cv - pl.w;
    __syncthreads();

    const float4* Cp = (const float4*)(g_C + (size_t)b * NN * NN) + (m0 >> 2) + g;
    float s0 = 0.f, s1 = 0.f, s2 = 0.f, s3 = 0.f;
    const int nbeg = p * 32;
#pragma unroll 4
    for (int n = nbeg; n < nbeg + 32; n++) {
        float4 c = Cp[(size_t)n * (NN / 4)];
        float lu = lu2s[n];
        s0 += exp2f(c.x + lu - V0.x);
        s1 += exp2f(c.y + lu - V0.y);
        s2 += exp2f(c.z + lu - V0.z);
        s3 += exp2f(c.w + lu - V0.w);
    }
    part[p][g] = make_float4(s0, s1, s2, s3);
    __syncthreads();

    if (t < 64) {
        int gg = t >> 2, j = t & 3;
        float s = 0.0f;
#pragma unroll
        for (int q = 0; q < 32; q++) s += ((float*)&part[q][gg])[j];
        float V = Cv - g_Lv2[b * NN + m0 + t];   // same (old) V0 for this column
        float LSE2 = V + log2f(fmaxf(s, 1e-38f));
        g_Lv2[b * NN + m0 + t] = Cv - LSE2;
    }
}

// ---------------- row pass ---------------------------------------------------
// Lu2_new[n] = Cu - (V0 + log2(sum_m exp2(C2[n,m] + Lv2[m] - V0)))
// 256 threads = 8 warps, warp per row.
__global__ void k_row() {
    __shared__ float4 lv2s[NN / 4];

    const int b = blockIdx.y;
    const int t = threadIdx.x;
    const int lane = t & 31;
    const int row  = blockIdx.x * 8 + (t >> 5);

    lv2s[t] = ((const float4*)(g_Lv2 + b * NN))[t];

    const float cminv2 = __uint_as_float(g_cminbits[b]) * g_inv_eps * LOG2E;
    const float Cu = cminv2 - 10.0f;
    const float V0 = Cu - g_Lu2[b * NN + row];
    __syncthreads();

    const float4* Crow = (const float4*)(g_C + ((size_t)(b * NN + row)) * NN);
    float s0 = 0.f, s1 = 0.f, s2 = 0.f, s3 = 0.f;
#pragma unroll
    for (int j = 0; j < 8; j++) {
        int i = lane + 32 * j;
        float4 c = Crow[i];
        float4 lv = lv2s[i];
        s0 += exp2f(c.x + lv.x - V0);
        s1 += exp2f(c.y + lv.y - V0);
        s2 += exp2f(c.z + lv.z - V0);
        s3 += exp2f(c.w + lv.w - V0);
    }
    float s = (s0 + s1) + (s2 + s3);
#pragma unroll
    for (int off = 16; off > 0; off >>= 1)
        s += __shfl_down_sync(0xFFFFFFFFu, s, off);
    if (lane == 0) {
        float LSE2 = V0 + log2f(fmaxf(s, 1e-38f));
        g_Lu2[b * NN + row] = Cu - LSE2;
    }
}

// ---------------- output -----------------------------------------------------
// w[n,m] = exp2(C2[n,m] + Lu2[n] + Lv2[m] - cminv2); out = (w @ y) / rowsum(w)
__global__ void k_out(const float* __restrict__ y, float* __restrict__ out) {
    __shared__ __align__(16) float ysm[64 * 64];
    __shared__ __align__(16) float wt[16 * 64];

    const int b  = blockIdx.y;
    const int n0 = blockIdx.x * 16;
    const int t  = threadIdx.x;
    const int r  = t >> 4;
    const int dg = t & 15;

    const float cminv2 = __uint_as_float(g_cminbits[b]) * g_inv_eps * LOG2E;

    float4 acc = make_float4(0.f, 0.f, 0.f, 0.f);
    float wsum = 0.0f;

    for (int mt = 0; mt < NN; mt += 64) {
#pragma unroll
        for (int r2 = 0; r2 < 4; r2++) {
            int fid = t + 256 * r2;
            int row = fid >> 4;
            int col4 = fid & 15;
            ((float4*)ysm)[fid] =
                *(const float4*)(y + ((size_t)(b * NN + mt + row)) * DD + col4 * 4);
        }
        {
            int wid = t * 4;
            int rw = wid >> 6;
            int mmw = wid & 63;
            float4 cv = *(const float4*)(g_C + ((size_t)(b * NN + n0 + rw)) * NN + mt + mmw);
            float4 lv = *(const float4*)(g_Lv2 + b * NN + mt + mmw);
            float lu = g_Lu2[b * NN + n0 + rw] - cminv2;
            float4 wv;
            wv.x = exp2f(cv.x + lv.x + lu);
            wv.y = exp2f(cv.y + lv.y + lu);
            wv.z = exp2f(cv.z + lv.z + lu);
            wv.w = exp2f(cv.w + lv.w + lu);
            *(float4*)(wt + wid) = wv;
        }
        __syncthreads();

#pragma unroll 16
        for (int mm = 0; mm < 64; mm++) {
            float w = wt[r * 64 + mm];
            float4 yv = *(const float4*)(ysm + mm * 64 + dg * 4);
            acc.x += w * yv.x;
            acc.y += w * yv.y;
            acc.z += w * yv.z;
            acc.w += w * yv.w;
            wsum += w;
        }
        __syncthreads();
    }

    float rinv = 1.0f / fmaxf(wsum, 1e-12f);
    float4 o;
    o.x = acc.x * rinv; o.y = acc.y * rinv;
    o.z = acc.z * rinv; o.w = acc.w * rinv;
    *(float4*)(out + ((size_t)(b * NN + n0 + r)) * DD + dg * 4) = o;
}

// ---------------- launcher ---------------------------------------------------
extern "C" void kernel_launch(void* const* d_in, const int* in_sizes, int n_in,
                              void* d_out, int out_size) {
    const float* x = (const float*)d_in[0];
    const float* y = (const float*)d_in[1];
    const void* eps = d_in[2];
    float* out = (float*)d_out;

    k_prep<<<(2 * BB * NN + 255) / 256, 256>>>(x, y, eps);
    k_gemm<<<dim3(NN / 64, NN / 64, BB), 256>>>(x, y);
    k_init<<<(BB * NN + 255) / 256, 256>>>();

    for (int it = 0; it < 50; it++) {
        k_col<<<dim3(NN / 64, BB), 512>>>();
        k_row<<<dim3(NN / 8, BB), 256>>>();
    }
    k_col<<<dim3(NN / 64, BB), 512>>>();  // final v-update

    k_out<<<dim3(NN / 16, BB), 256>>>(y, out);
}